// round 5
// baseline (speedup 1.0000x reference)
#include <cuda_runtime.h>
#include <cuda_bf16.h>
#include <cstddef>

// B=4, S=2048, D=1024, I=1024. Keys are broadcast-identical -> softmax == 1/S
// exactly -> out[b,s,:] = ((mean_s x[b,s,:]) @ Wv) @ Wo, independent of s.
//
// Persistent kernel, 128 blocks x 1024 threads (co-resident, spin barriers
// safe). Batch-pair software pipeline: the 16MB output write of pair 0
// overlaps the 16MB input read of pair 1 (block specialization in P4).
// R5 fix: s_red must hold 1024 float4 (4096 floats) for the colsum reduce —
// R4 declared 2048 and overran shared memory.

#define SEQ   2048
#define DIM   1024
#define IDIM  1024
#define NBLK  128
#define NTHR  1024
#define NBAR  6

__device__ float g_part[4 * 64 * DIM];   // colsum partials (<=64 splits/batch)
__device__ float g_tp  [4 * 16 * IDIM];  // gemv1 partials (16 d-slices)
__device__ float g_yp  [4 * 16 * DIM];   // gemv2 partials

__device__ unsigned g_bar_cnt[NBAR];
__device__ unsigned g_bar_gen[NBAR];

__device__ __forceinline__ void grid_barrier(int i) {
    __syncthreads();
    if (threadIdx.x == 0) {
        __threadfence();
        unsigned g = *(volatile unsigned*)&g_bar_gen[i];
        unsigned old = atomicAdd(&g_bar_cnt[i], 1u);
        if (old == NBLK - 1) {
            g_bar_cnt[i] = 0;
            __threadfence();
            atomicAdd(&g_bar_gen[i], 1u);
        } else {
            while (*(volatile unsigned*)&g_bar_gen[i] == g) { __nanosleep(32); }
        }
        __threadfence();
    }
    __syncthreads();
}

// ---- colsum over a batch pair. nblk_phase in {64,128}. --------------------
// rows_per_block = 4096/nblk_phase (32 or 64); splits/batch = 2048/rpb.
__device__ __forceinline__ void colsum_pair(const float* __restrict__ x,
                                            float* s_red,
                                            int pair, int blk_rel, int nblk_phase) {
    const int tid = threadIdx.x;
    const int rpb = 4096 / nblk_phase;
    const int gr  = blk_rel * rpb;            // row within pair [0,4096)
    const int b   = pair * 2 + (gr >> 11);
    const int s   = gr & 2047;
    const int sp  = s / rpb;
    const int r4  = tid >> 8;                 // 0..3
    const int c   = tid & 255;
    const int nr  = rpb >> 2;                 // 8 or 16

    const float4* xp = reinterpret_cast<const float4*>(x)
                     + (size_t)(b * SEQ + s + r4) * 256 + c;
    float4 acc = make_float4(0.f, 0.f, 0.f, 0.f);
#pragma unroll 16
    for (int i = 0; i < nr; ++i) {
        float4 v = xp[(size_t)i * 4 * 256];
        acc.x += v.x; acc.y += v.y; acc.z += v.z; acc.w += v.w;
    }
    float4* sb4 = reinterpret_cast<float4*>(s_red);
    sb4[tid] = acc;                           // 1024 float4 = 4096 floats
    __syncthreads();
    if (tid < 256) {
        float4 a = sb4[tid], b1 = sb4[tid + 256],
               c1 = sb4[tid + 512], d1 = sb4[tid + 768];
        float4 r = make_float4(a.x + b1.x + c1.x + d1.x,
                               a.y + b1.y + c1.y + d1.y,
                               a.z + b1.z + c1.z + d1.z,
                               a.w + b1.w + c1.w + d1.w);
        reinterpret_cast<float4*>(g_part)[(b * 64 + sp) * 256 + tid] = r;
    }
}

// ---- gemv1: t_partial[b][ds][i] for both batches of a pair. ---------------
__device__ __forceinline__ void gemv1_pair(const float* __restrict__ Wv,
                                           float* s_red, float* s_xs,
                                           int pair, int nsplits) {
    const int tid = threadIdx.x;
    const int blk = blockIdx.x;
    const int ds = blk >> 3, ic = blk & 7;
    const int d0 = ds * 64;

    if (tid < 512) {                          // split gather: 4 ways per (bb,dd)
        const int q = tid >> 7, rem = tid & 127;
        const int bb = rem >> 6, dd = rem & 63;
        const int per = nsplits >> 2;
        const int base = ((pair * 2 + bb) * 64 + q * per) * DIM + d0 + dd;
        float s = 0.f;
#pragma unroll 16
        for (int p = 0; p < per; ++p) s += g_part[base + p * DIM];
        s_red[q * 128 + rem] = s;
    }
    __syncthreads();
    if (tid < 128)
        s_xs[tid] = (s_red[tid] + s_red[128 + tid] + s_red[256 + tid] + s_red[384 + tid])
                  * (1.0f / (float)SEQ);
    __syncthreads();

    const int dg = tid >> 7, il = tid & 127;
    const int i  = ic * 128 + il;
    float a0 = 0.f, a1 = 0.f;
#pragma unroll
    for (int dd = 0; dd < 8; ++dd) {
        const int dl = dg * 8 + dd;
        const float w = __ldg(&Wv[(size_t)(d0 + dl) * IDIM + i]);
        a0 += s_xs[dl]      * w;
        a1 += s_xs[64 + dl] * w;
    }
    __syncthreads();                          // s_red reuse
    s_red[dg * 128 + il]        = a0;
    s_red[1024 + dg * 128 + il] = a1;
    __syncthreads();
    if (tid < 256) {
        const int bb = tid >> 7, il2 = tid & 127;
        float s = 0.f;
#pragma unroll
        for (int g = 0; g < 8; ++g) s += s_red[bb * 1024 + g * 128 + il2];
        g_tp[((pair * 2 + bb) * 16 + ds) * IDIM + ic * 128 + il2] = s;
    }
}

// ---- gemv2: y_partial[b][is][o] for both batches of a pair. ---------------
__device__ __forceinline__ void gemv2_pair(const float* __restrict__ Wo,
                                           float* s_red, float* s_xs, int pair) {
    const int tid = threadIdx.x;
    const int blk = blockIdx.x;
    const int is = blk >> 3, ic = blk & 7;
    const int i0 = is * 64;

    if (tid < 512) {
        const int q = tid >> 7, rem = tid & 127;
        const int bb = rem >> 6, ii = rem & 63;
        const int base = ((pair * 2 + bb) * 16 + q * 4) * IDIM + i0 + ii;
        float s = 0.f;
#pragma unroll
        for (int p = 0; p < 4; ++p) s += g_tp[base + p * IDIM];
        s_red[q * 128 + rem] = s;
    }
    __syncthreads();
    if (tid < 128)
        s_xs[tid] = s_red[tid] + s_red[128 + tid] + s_red[256 + tid] + s_red[384 + tid];
    __syncthreads();

    const int ig = tid >> 7, ol = tid & 127;
    const int o  = ic * 128 + ol;
    float a0 = 0.f, a1 = 0.f;
#pragma unroll
    for (int ii = 0; ii < 8; ++ii) {
        const int il = ig * 8 + ii;
        const float w = __ldg(&Wo[(size_t)(i0 + il) * DIM + o]);
        a0 += s_xs[il]      * w;
        a1 += s_xs[64 + il] * w;
    }
    __syncthreads();
    s_red[ig * 128 + ol]        = a0;
    s_red[1024 + ig * 128 + ol] = a1;
    __syncthreads();
    if (tid < 256) {
        const int bb = tid >> 7, ol2 = tid & 127;
        float s = 0.f;
#pragma unroll
        for (int g = 0; g < 8; ++g) s += s_red[bb * 1024 + g * 128 + ol2];
        g_yp[((pair * 2 + bb) * 16 + is) * DIM + ic * 128 + ol2] = s;
    }
}

// ---- finalize y[b] + broadcast rows. nblk_phase in {64,128}. --------------
__device__ __forceinline__ void write_pair(float* __restrict__ out,
                                           float* s_red,
                                           int pair, int blk_rel, int nblk_phase) {
    const int tid = threadIdx.x;
    const int rpb = 4096 / nblk_phase;        // 32 or 64 rows per block
    const int gr  = blk_rel * rpb;
    const int b   = pair * 2 + (gr >> 11);
    const int s   = gr & 2047;

    float acc = 0.f;
#pragma unroll
    for (int p = 0; p < 16; ++p) acc += g_yp[(b * 16 + p) * DIM + tid];
    s_red[tid] = acc;
    __syncthreads();

    const int r4 = tid >> 8, c = tid & 255;
    const int nr = rpb >> 2;
    const float4 v = reinterpret_cast<const float4*>(s_red)[c];
    float4* o4 = reinterpret_cast<float4*>(out)
               + (size_t)(b * SEQ + s + r4) * 256 + c;
#pragma unroll 16
    for (int i = 0; i < nr; ++i)
        o4[(size_t)i * 4 * 256] = v;
}

__global__ void __launch_bounds__(NTHR, 1)
fusion_pipelined(const float* __restrict__ x,
                 const float* __restrict__ Wv,
                 const float* __restrict__ Wo,
                 float* __restrict__ out) {
    const int blk = blockIdx.x;
    __shared__ __align__(16) float s_red[4096];  // 16 KB (colsum needs all)
    __shared__ float s_xs[128];

    // Pair 0: b0,b1
    colsum_pair(x, s_red, 0, blk, 128);        grid_barrier(0);
    gemv1_pair(Wv, s_red, s_xs, 0, 64);        grid_barrier(1);
    gemv2_pair(Wo, s_red, s_xs, 0);            grid_barrier(2);

    // Overlap: write pair 0 (blocks 0-63) || colsum pair 1 (blocks 64-127)
    if (blk < 64) write_pair(out, s_red, 0, blk, 64);
    else          colsum_pair(x, s_red, 1, blk - 64, 64);
    grid_barrier(3);

    // Pair 1: b2,b3
    gemv1_pair(Wv, s_red, s_xs, 1, 32);        grid_barrier(4);
    gemv2_pair(Wo, s_red, s_xs, 1);            grid_barrier(5);
    write_pair(out, s_red, 1, blk, 128);
}

// Inputs: 0=inputs_embeds [B,S,D] f32, 1=structure_features, 2=Wq, 3=Wk,
// 4=Wv [D,I] f32, 5=Wo [I,D] f32, 6=num_heads. Only x, Wv, Wo matter.
extern "C" void kernel_launch(void* const* d_in, const int* in_sizes, int n_in,
                              void* d_out, int out_size) {
    (void)in_sizes; (void)n_in; (void)out_size;
    const float* x  = (const float*)d_in[0];
    const float* Wv = (const float*)d_in[4];
    const float* Wo = (const float*)d_in[5];
    fusion_pipelined<<<NBLK, NTHR>>>(x, Wv, Wo, (float*)d_out);
}

// round 6
// speedup vs baseline: 1.2630x; 1.2630x over previous
#include <cuda_runtime.h>
#include <cuda_bf16.h>
#include <cstddef>

// B=4, S=2048, D=1024, I=1024. Keys are broadcast-identical -> softmax == 1/S
// exactly -> out[b,s,:] = ((mean_s x[b,s,:]) @ Wv) @ Wo, independent of s.
//
// Persistent kernel, 148 blocks x 1024 threads (1 block/SM on all SMs,
// co-resident => spin grid-barriers safe). 4 phases / 3 barriers.
// Big streaming phases (P1 read, P4 write) use all 148 blocks with
// variable-length row splits (37 splits/batch, 55-56 rows each).
// GEMV phases use blocks 0..127; gathers parallelized over all 1024 threads.

#define SEQ   2048
#define DIM   1024
#define IDIM  1024
#define NBLK  148
#define NTHR  1024
#define SPB   37        // row-splits per batch (4*37 = 148)
#define NBAR  3

__device__ float g_part[4 * SPB * DIM];  // colsum partials
__device__ float g_tp  [4 * 16 * IDIM];  // gemv1 partials (16 d-slices)
__device__ float g_yp  [4 * 16 * DIM];   // gemv2 partials

__device__ unsigned g_bar_cnt[NBAR];
__device__ unsigned g_bar_gen[NBAR];

__device__ __forceinline__ void grid_barrier(int i) {
    __syncthreads();
    if (threadIdx.x == 0) {
        __threadfence();
        unsigned g = *(volatile unsigned*)&g_bar_gen[i];
        unsigned old = atomicAdd(&g_bar_cnt[i], 1u);
        if (old == NBLK - 1) {
            g_bar_cnt[i] = 0;
            __threadfence();
            atomicAdd(&g_bar_gen[i], 1u);
        } else {
            while (*(volatile unsigned*)&g_bar_gen[i] == g) { __nanosleep(32); }
        }
        __threadfence();
    }
    __syncthreads();
}

__global__ void __launch_bounds__(NTHR, 1)
fusion_persistent(const float* __restrict__ x,
                  const float* __restrict__ Wv,
                  const float* __restrict__ Wo,
                  float* __restrict__ out) {
    const int blk = blockIdx.x;
    const int tid = threadIdx.x;

    __shared__ __align__(16) float s_red[4096];  // 16 KB
    __shared__ float s_xs[256];                  // xbar / t slices (4 batches x 64)

    // Split geometry for P1/P4: block -> (b, sp) with variable row range.
    const int b_sp  = blk / SPB;                 // batch 0..3
    const int sp    = blk - b_sp * SPB;          // split 0..36
    const int rs    = (sp * SEQ) / SPB;          // start row
    const int re    = ((sp + 1) * SEQ) / SPB;    // end row
    const int nrows = re - rs;                   // 55 or 56

    // ---------------- Phase 1: column-sum partials of x --------------------
    {
        const int r4 = tid >> 8;                 // 0..3 rows in flight
        const int c  = tid & 255;                // float4 column
        const float4* xp = reinterpret_cast<const float4*>(x)
                         + (size_t)(b_sp * SEQ + rs) * 256 + c;
        float4 acc = make_float4(0.f, 0.f, 0.f, 0.f);
#pragma unroll 7
        for (int r = r4; r < nrows; r += 4) {
            float4 v = xp[(size_t)r * 256];
            acc.x += v.x; acc.y += v.y; acc.z += v.z; acc.w += v.w;
        }
        float4* sb4 = reinterpret_cast<float4*>(s_red);
        sb4[tid] = acc;
        __syncthreads();
        if (tid < 256) {
            float4 a = sb4[tid], b1 = sb4[tid + 256],
                   c1 = sb4[tid + 512], d1 = sb4[tid + 768];
            float4 r = make_float4(a.x + b1.x + c1.x + d1.x,
                                   a.y + b1.y + c1.y + d1.y,
                                   a.z + b1.z + c1.z + d1.z,
                                   a.w + b1.w + c1.w + d1.w);
            reinterpret_cast<float4*>(g_part)[(b_sp * SPB + sp) * 256 + tid] = r;
        }
    }
    grid_barrier(0);

    // ---------------- Phase 2: t = xbar @ Wv (blocks 0..127) ---------------
    // Block = (ds 0..15, ic 0..7). d-slice of 64, i-chunk of 128.
    if (blk < 128) {
        const int ds = blk >> 3, ic = blk & 7;
        const int d0 = ds * 64;

        // Gather xbar[bb][d0+dd]: 4-way split-parallel over 37 partials.
        {
            const int q  = tid >> 8;             // 0..3
            const int rem = tid & 255;           // (bb,dd)
            const int bb = rem >> 6, dd = rem & 63;
            float s = 0.f;
            for (int p = q; p < SPB; p += 4)
                s += g_part[(bb * SPB + p) * DIM + d0 + dd];
            s_red[q * 256 + rem] = s;
        }
        __syncthreads();
        if (tid < 256)
            s_xs[tid] = (s_red[tid] + s_red[256 + tid] +
                         s_red[512 + tid] + s_red[768 + tid]) * (1.0f / (float)SEQ);
        __syncthreads();

        const int dg = tid >> 7, il = tid & 127;
        const int i  = ic * 128 + il;
        float a0 = 0.f, a1 = 0.f, a2 = 0.f, a3 = 0.f;
#pragma unroll
        for (int dd = 0; dd < 8; ++dd) {
            const int dl = dg * 8 + dd;
            const float w = __ldg(&Wv[(size_t)(d0 + dl) * IDIM + i]);
            a0 += s_xs[dl]       * w;
            a1 += s_xs[64 + dl]  * w;
            a2 += s_xs[128 + dl] * w;
            a3 += s_xs[192 + dl] * w;
        }
        __syncthreads();
        s_red[(0 * 8 + dg) * 128 + il] = a0;
        s_red[(1 * 8 + dg) * 128 + il] = a1;
        s_red[(2 * 8 + dg) * 128 + il] = a2;
        s_red[(3 * 8 + dg) * 128 + il] = a3;
        __syncthreads();
        if (tid < 512) {
            const int bb = tid >> 7, il2 = tid & 127;
            float s = 0.f;
#pragma unroll
            for (int g = 0; g < 8; ++g) s += s_red[(bb * 8 + g) * 128 + il2];
            g_tp[(bb * 16 + ds) * IDIM + ic * 128 + il2] = s;
        }
    }
    grid_barrier(1);

    // ---------------- Phase 3: y = t @ Wo (blocks 0..127) ------------------
    if (blk < 128) {
        const int is = blk >> 3, ic = blk & 7;
        const int i0 = is * 64;

        {
            const int q  = tid >> 8;
            const int rem = tid & 255;
            const int bb = rem >> 6, ii = rem & 63;
            float s = 0.f;
#pragma unroll
            for (int p = 0; p < 4; ++p)
                s += g_tp[(bb * 16 + q * 4 + p) * IDIM + i0 + ii];
            s_red[q * 256 + rem] = s;
        }
        __syncthreads();
        if (tid < 256)
            s_xs[tid] = s_red[tid] + s_red[256 + tid] +
                        s_red[512 + tid] + s_red[768 + tid];
        __syncthreads();

        const int ig = tid >> 7, ol = tid & 127;
        const int o  = ic * 128 + ol;
        float a0 = 0.f, a1 = 0.f, a2 = 0.f, a3 = 0.f;
#pragma unroll
        for (int ii = 0; ii < 8; ++ii) {
            const int il = ig * 8 + ii;
            const float w = __ldg(&Wo[(size_t)(i0 + il) * DIM + o]);
            a0 += s_xs[il]       * w;
            a1 += s_xs[64 + il]  * w;
            a2 += s_xs[128 + il] * w;
            a3 += s_xs[192 + il] * w;
        }
        __syncthreads();
        s_red[(0 * 8 + ig) * 128 + ol] = a0;
        s_red[(1 * 8 + ig) * 128 + ol] = a1;
        s_red[(2 * 8 + ig) * 128 + ol] = a2;
        s_red[(3 * 8 + ig) * 128 + ol] = a3;
        __syncthreads();
        if (tid < 512) {
            const int bb = tid >> 7, ol2 = tid & 127;
            float s = 0.f;
#pragma unroll
            for (int g = 0; g < 8; ++g) s += s_red[(bb * 8 + g) * 128 + ol2];
            g_yp[(bb * 16 + is) * DIM + ic * 128 + ol2] = s;
        }
    }
    grid_barrier(2);

    // ---------------- Phase 4: finalize y[b] + broadcast rows --------------
    {
        float acc = 0.f;
#pragma unroll
        for (int p = 0; p < 16; ++p)
            acc += g_yp[(b_sp * 16 + p) * DIM + tid];
        s_red[tid] = acc;
        __syncthreads();

        const int r4 = tid >> 8, c = tid & 255;
        const float4 v = reinterpret_cast<const float4*>(s_red)[c];
        float4* o4 = reinterpret_cast<float4*>(out)
                   + (size_t)(b_sp * SEQ + rs) * 256 + c;
#pragma unroll 7
        for (int r = r4; r < nrows; r += 4)
            o4[(size_t)r * 256] = v;
    }
}

// Inputs: 0=inputs_embeds [B,S,D] f32, 1=structure_features, 2=Wq, 3=Wk,
// 4=Wv [D,I] f32, 5=Wo [I,D] f32, 6=num_heads. Only x, Wv, Wo matter.
extern "C" void kernel_launch(void* const* d_in, const int* in_sizes, int n_in,
                              void* d_out, int out_size) {
    (void)in_sizes; (void)n_in; (void)out_size;
    const float* x  = (const float*)d_in[0];
    const float* Wv = (const float*)d_in[4];
    const float* Wo = (const float*)d_in[5];
    fusion_persistent<<<NBLK, NTHR>>>(x, Wv, Wo, (float*)d_out);
}

// round 7
// speedup vs baseline: 1.4706x; 1.1644x over previous
#include <cuda_runtime.h>
#include <cuda_bf16.h>
#include <cstddef>

// B=4, S=2048, D=1024, I=1024. Keys are broadcast-identical -> softmax == 1/S
// exactly -> out[b,s,:] = ((mean_s x[b,s,:]) @ Wv) @ Wo, independent of s.
//
// Persistent kernel, 128 blocks x 1024 threads (co-resident, spin barriers
// safe), 4 phases / 3 barriers. R7: R3 skeleton (compile-time unrolled loads)
// + weight-LDG hoisted above the syncs + 4-way parallel gathers + tight spin.

#define SEQ   2048
#define DIM   1024
#define IDIM  1024
#define NBLK  128
#define NTHR  1024
#define SPB   32      // row-splits per batch (64 rows each)
#define NBAR  3

__device__ float g_part[4 * SPB * DIM];  // 512 KB colsum partials
__device__ float g_tp  [4 * 16 * IDIM];  // gemv1 partials (16 d-slices)
__device__ float g_yp  [4 * 16 * DIM];   // gemv2 partials

__device__ unsigned g_bar_cnt[NBAR];
__device__ unsigned g_bar_gen[NBAR];

__device__ __forceinline__ void grid_barrier(int i) {
    __syncthreads();
    if (threadIdx.x == 0) {
        __threadfence();
        unsigned g = *(volatile unsigned*)&g_bar_gen[i];
        unsigned old = atomicAdd(&g_bar_cnt[i], 1u);
        if (old == NBLK - 1) {
            g_bar_cnt[i] = 0;
            __threadfence();
            atomicAdd(&g_bar_gen[i], 1u);
        } else {
            while (*(volatile unsigned*)&g_bar_gen[i] == g) { }  // tight spin
        }
        __threadfence();
    }
    __syncthreads();
}

__global__ void __launch_bounds__(NTHR, 1)
fusion_persistent(const float* __restrict__ x,
                  const float* __restrict__ Wv,
                  const float* __restrict__ Wo,
                  float* __restrict__ out) {
    const int blk = blockIdx.x;
    const int tid = threadIdx.x;

    __shared__ __align__(16) float s_red[4096];  // 16 KB
    __shared__ float s_xs[256];                  // 4 batches x 64 slice values

    // ---------------- Phase 1: column-sum partials of x --------------------
    // Block = (b, sp): 64 rows x 1024 cols. 16 independent float4 loads/thread.
    {
        const int b  = blk >> 5;
        const int sp = blk & 31;
        const int r4 = tid >> 8;                 // 0..3
        const int c  = tid & 255;
        const float4* xp = reinterpret_cast<const float4*>(x)
                         + (size_t)(b * SEQ + sp * 64 + r4) * 256 + c;
        float4 acc = make_float4(0.f, 0.f, 0.f, 0.f);
#pragma unroll
        for (int r = 0; r < 16; ++r) {
            float4 v = xp[(size_t)r * 4 * 256];
            acc.x += v.x; acc.y += v.y; acc.z += v.z; acc.w += v.w;
        }
        float4* sb4 = reinterpret_cast<float4*>(s_red);
        sb4[tid] = acc;
        __syncthreads();
        if (tid < 256) {
            float4 a = sb4[tid], b1 = sb4[tid + 256],
                   c1 = sb4[tid + 512], d1 = sb4[tid + 768];
            float4 r = make_float4(a.x + b1.x + c1.x + d1.x,
                                   a.y + b1.y + c1.y + d1.y,
                                   a.z + b1.z + c1.z + d1.z,
                                   a.w + b1.w + c1.w + d1.w);
            reinterpret_cast<float4*>(g_part)[(b * SPB + sp) * 256 + tid] = r;
        }
    }
    grid_barrier(0);

    // ---------------- Phase 2: t = xbar @ Wv ------------------------------
    // Block = (ds 0..15, ic 0..7). Weight loads issued FIRST (independent of
    // the gather/syncs) so they overlap the L2 gather chain.
    {
        const int ds = blk >> 3, ic = blk & 7;
        const int d0 = ds * 64;
        const int dg = tid >> 7, il = tid & 127;
        const int i  = ic * 128 + il;

        float w[8];
#pragma unroll
        for (int dd = 0; dd < 8; ++dd)
            w[dd] = __ldg(&Wv[(size_t)(d0 + dg * 8 + dd) * IDIM + i]);

        // 4-way parallel gather of xbar slice (8 compile-time loads each).
        {
            const int q  = tid >> 8;             // 0..3
            const int rem = tid & 255;           // (bb, dm)
            const int bb = rem >> 6, dm = rem & 63;
            float s = 0.f;
#pragma unroll
            for (int p = 0; p < 8; ++p)
                s += g_part[(bb * SPB + q * 8 + p) * DIM + d0 + dm];
            s_red[q * 256 + rem] = s;
        }
        __syncthreads();
        if (tid < 256)
            s_xs[tid] = (s_red[tid] + s_red[256 + tid] +
                         s_red[512 + tid] + s_red[768 + tid]) * (1.0f / (float)SEQ);
        __syncthreads();

        float a0 = 0.f, a1 = 0.f, a2 = 0.f, a3 = 0.f;
#pragma unroll
        for (int dd = 0; dd < 8; ++dd) {
            const int dl = dg * 8 + dd;
            a0 += s_xs[dl]       * w[dd];
            a1 += s_xs[64 + dl]  * w[dd];
            a2 += s_xs[128 + dl] * w[dd];
            a3 += s_xs[192 + dl] * w[dd];
        }
        __syncthreads();
        s_red[(0 * 8 + dg) * 128 + il] = a0;
        s_red[(1 * 8 + dg) * 128 + il] = a1;
        s_red[(2 * 8 + dg) * 128 + il] = a2;
        s_red[(3 * 8 + dg) * 128 + il] = a3;
        __syncthreads();
        if (tid < 512) {
            const int bb = tid >> 7, il2 = tid & 127;
            float s = 0.f;
#pragma unroll
            for (int g = 0; g < 8; ++g) s += s_red[(bb * 8 + g) * 128 + il2];
            g_tp[(bb * 16 + ds) * IDIM + ic * 128 + il2] = s;
        }
    }
    grid_barrier(1);

    // ---------------- Phase 3: y = t @ Wo ---------------------------------
    {
        const int is = blk >> 3, ic = blk & 7;
        const int i0 = is * 64;
        const int ig = tid >> 7, ol = tid & 127;
        const int o  = ic * 128 + ol;

        float w[8];
#pragma unroll
        for (int ii = 0; ii < 8; ++ii)
            w[ii] = __ldg(&Wo[(size_t)(i0 + ig * 8 + ii) * DIM + o]);

        {
            const int q  = tid >> 8;
            const int rem = tid & 255;
            const int bb = rem >> 6, im = rem & 63;
            float s = 0.f;
#pragma unroll
            for (int p = 0; p < 4; ++p)
                s += g_tp[(bb * 16 + q * 4 + p) * IDIM + i0 + im];
            s_red[q * 256 + rem] = s;
        }
        __syncthreads();
        if (tid < 256)
            s_xs[tid] = s_red[tid] + s_red[256 + tid] +
                        s_red[512 + tid] + s_red[768 + tid];
        __syncthreads();

        float a0 = 0.f, a1 = 0.f, a2 = 0.f, a3 = 0.f;
#pragma unroll
        for (int ii = 0; ii < 8; ++ii) {
            const int il = ig * 8 + ii;
            a0 += s_xs[il]       * w[ii];
            a1 += s_xs[64 + il]  * w[ii];
            a2 += s_xs[128 + il] * w[ii];
            a3 += s_xs[192 + il] * w[ii];
        }
        __syncthreads();
        s_red[(0 * 8 + ig) * 128 + ol] = a0;
        s_red[(1 * 8 + ig) * 128 + ol] = a1;
        s_red[(2 * 8 + ig) * 128 + ol] = a2;
        s_red[(3 * 8 + ig) * 128 + ol] = a3;
        __syncthreads();
        if (tid < 512) {
            const int bb = tid >> 7, ol2 = tid & 127;
            float s = 0.f;
#pragma unroll
            for (int g = 0; g < 8; ++g) s += s_red[(bb * 8 + g) * 128 + ol2];
            g_yp[(bb * 16 + is) * DIM + ic * 128 + ol2] = s;
        }
    }
    grid_barrier(2);

    // ---------------- Phase 4: finalize y[b] + broadcast 64 rows -----------
    {
        const int b  = blk >> 5;
        const int sb = blk & 31;

        float acc = 0.f;
#pragma unroll
        for (int p = 0; p < 16; ++p)
            acc += g_yp[(b * 16 + p) * DIM + tid];
        s_red[tid] = acc;
        __syncthreads();

        const int r4 = tid >> 8, c = tid & 255;
        const float4 v = reinterpret_cast<const float4*>(s_red)[c];
        float4* o4 = reinterpret_cast<float4*>(out)
                   + (size_t)(b * SEQ + sb * 64 + r4) * 256 + c;
#pragma unroll
        for (int r = 0; r < 16; ++r)
            o4[(size_t)r * 4 * 256] = v;
    }
}

// Inputs: 0=inputs_embeds [B,S,D] f32, 1=structure_features, 2=Wq, 3=Wk,
// 4=Wv [D,I] f32, 5=Wo [I,D] f32, 6=num_heads. Only x, Wv, Wo matter.
extern "C" void kernel_launch(void* const* d_in, const int* in_sizes, int n_in,
                              void* d_out, int out_size) {
    (void)in_sizes; (void)n_in; (void)out_size;
    const float* x  = (const float*)d_in[0];
    const float* Wv = (const float*)d_in[4];
    const float* Wo = (const float*)d_in[5];
    fusion_persistent<<<NBLK, NTHR>>>(x, Wv, Wo, (float*)d_out);
}

// round 8
// speedup vs baseline: 1.4863x; 1.0107x over previous
#include <cuda_runtime.h>
#include <cuda_bf16.h>
#include <cstddef>

// B=4, S=2048, D=1024, I=1024. Keys are broadcast-identical -> softmax == 1/S
// exactly -> out[b,s,:] = ((mean_s x[b,s,:]) @ Wv) @ Wo, independent of s.
//
// Persistent kernel, 128 blocks x 1024 threads, 4 phases / 3 barriers.
// R8: (1) __stcs streaming stores so the 32MB output drains during P4 instead
// of colliding with the next replay's read phase; (2) split barrier
// arrive/wait with weight prefetch inside the wait window; (3) 4 independent
// accumulator chains in P1 for guaranteed front-batched MLP.

#define SEQ   2048
#define DIM   1024
#define IDIM  1024
#define NBLK  128
#define NTHR  1024
#define SPB   32
#define NBAR  3

__device__ float g_part[4 * SPB * DIM];  // 512 KB colsum partials
__device__ float g_tp  [4 * 16 * IDIM];  // gemv1 partials
__device__ float g_yp  [4 * 16 * DIM];   // gemv2 partials

__device__ unsigned g_bar_cnt[NBAR];
__device__ unsigned g_bar_gen[NBAR];

// Split barrier: arrive (release) ... independent work ... wait (acquire).
__device__ __forceinline__ void bar_arrive(int i, unsigned& gen) {
    __syncthreads();
    if (threadIdx.x == 0) {
        __threadfence();
        gen = *(volatile unsigned*)&g_bar_gen[i];
        unsigned old = atomicAdd(&g_bar_cnt[i], 1u);
        if (old == NBLK - 1) {
            g_bar_cnt[i] = 0;
            __threadfence();
            atomicAdd(&g_bar_gen[i], 1u);
        }
    }
}
__device__ __forceinline__ void bar_wait(int i, unsigned gen) {
    if (threadIdx.x == 0) {
        while (*(volatile unsigned*)&g_bar_gen[i] == gen) { }
        __threadfence();
    }
    __syncthreads();
}

__global__ void __launch_bounds__(NTHR, 1)
fusion_persistent(const float* __restrict__ x,
                  const float* __restrict__ Wv,
                  const float* __restrict__ Wo,
                  float* __restrict__ out) {
    const int blk = blockIdx.x;
    const int tid = threadIdx.x;
    unsigned gen0 = 0, gen1 = 0, gen2 = 0;

    __shared__ __align__(16) float s_red[4096];  // 16 KB
    __shared__ float s_xs[256];

    // ---------------- Phase 1: column-sum partials of x --------------------
    {
        const int b  = blk >> 5;
        const int sp = blk & 31;
        const int r4 = tid >> 8;
        const int c  = tid & 255;
        const float4* xp = reinterpret_cast<const float4*>(x)
                         + (size_t)(b * SEQ + sp * 64 + r4) * 256 + c;
        // 4 independent accumulator chains, 16 front-batched loads.
        float4 a0 = make_float4(0.f,0.f,0.f,0.f), a1 = a0, a2 = a0, a3 = a0;
#pragma unroll
        for (int k = 0; k < 4; ++k) {
            float4 v0 = xp[(size_t)(4 * k + 0) * 1024];
            float4 v1 = xp[(size_t)(4 * k + 1) * 1024];
            float4 v2 = xp[(size_t)(4 * k + 2) * 1024];
            float4 v3 = xp[(size_t)(4 * k + 3) * 1024];
            a0.x += v0.x; a0.y += v0.y; a0.z += v0.z; a0.w += v0.w;
            a1.x += v1.x; a1.y += v1.y; a1.z += v1.z; a1.w += v1.w;
            a2.x += v2.x; a2.y += v2.y; a2.z += v2.z; a2.w += v2.w;
            a3.x += v3.x; a3.y += v3.y; a3.z += v3.z; a3.w += v3.w;
        }
        float4 acc = make_float4(a0.x + a1.x + a2.x + a3.x,
                                 a0.y + a1.y + a2.y + a3.y,
                                 a0.z + a1.z + a2.z + a3.z,
                                 a0.w + a1.w + a2.w + a3.w);
        float4* sb4 = reinterpret_cast<float4*>(s_red);
        sb4[tid] = acc;
        __syncthreads();
        if (tid < 256) {
            float4 a = sb4[tid], b1 = sb4[tid + 256],
                   c1 = sb4[tid + 512], d1 = sb4[tid + 768];
            float4 r = make_float4(a.x + b1.x + c1.x + d1.x,
                                   a.y + b1.y + c1.y + d1.y,
                                   a.z + b1.z + c1.z + d1.z,
                                   a.w + b1.w + c1.w + d1.w);
            reinterpret_cast<float4*>(g_part)[(b * SPB + sp) * 256 + tid] = r;
        }
    }
    bar_arrive(0, gen0);

    // ---------------- Phase 2: t = xbar @ Wv ------------------------------
    const int ds = blk >> 3, ic = blk & 7;
    const int d0 = ds * 64;
    const int dg = tid >> 7, il = tid & 127;
    const int i2 = ic * 128 + il;

    // Prefetch Wv inside the barrier-wait window (independent of g_part).
    float w[8];
#pragma unroll
    for (int dd = 0; dd < 8; ++dd)
        w[dd] = __ldg(&Wv[(size_t)(d0 + dg * 8 + dd) * IDIM + i2]);

    bar_wait(0, gen0);
    {
        {
            const int q  = tid >> 8;
            const int rem = tid & 255;
            const int bb = rem >> 6, dm = rem & 63;
            float s = 0.f;
#pragma unroll
            for (int p = 0; p < 8; ++p)
                s += g_part[(bb * SPB + q * 8 + p) * DIM + d0 + dm];
            s_red[q * 256 + rem] = s;
        }
        __syncthreads();
        if (tid < 256)
            s_xs[tid] = (s_red[tid] + s_red[256 + tid] +
                         s_red[512 + tid] + s_red[768 + tid]) * (1.0f / (float)SEQ);
        __syncthreads();

        float a0 = 0.f, a1 = 0.f, a2 = 0.f, a3 = 0.f;
#pragma unroll
        for (int dd = 0; dd < 8; ++dd) {
            const int dl = dg * 8 + dd;
            a0 += s_xs[dl]       * w[dd];
            a1 += s_xs[64 + dl]  * w[dd];
            a2 += s_xs[128 + dl] * w[dd];
            a3 += s_xs[192 + dl] * w[dd];
        }
        __syncthreads();
        s_red[(0 * 8 + dg) * 128 + il] = a0;
        s_red[(1 * 8 + dg) * 128 + il] = a1;
        s_red[(2 * 8 + dg) * 128 + il] = a2;
        s_red[(3 * 8 + dg) * 128 + il] = a3;
        __syncthreads();
        if (tid < 512) {
            const int bb = tid >> 7, il2 = tid & 127;
            float s = 0.f;
#pragma unroll
            for (int g = 0; g < 8; ++g) s += s_red[(bb * 8 + g) * 128 + il2];
            g_tp[(bb * 16 + ds) * IDIM + ic * 128 + il2] = s;
        }
    }
    bar_arrive(1, gen1);

    // ---------------- Phase 3: y = t @ Wo ---------------------------------
    // (same block geometry: is=ds, i0=d0, o=i2)
#pragma unroll
    for (int ii = 0; ii < 8; ++ii)   // prefetch Wo in the wait window
        w[ii] = __ldg(&Wo[(size_t)(d0 + dg * 8 + ii) * DIM + i2]);

    bar_wait(1, gen1);
    {
        {
            const int q  = tid >> 8;
            const int rem = tid & 255;
            const int bb = rem >> 6, im = rem & 63;
            float s = 0.f;
#pragma unroll
            for (int p = 0; p < 4; ++p)
                s += g_tp[(bb * 16 + q * 4 + p) * IDIM + d0 + im];
            s_red[q * 256 + rem] = s;
        }
        __syncthreads();
        if (tid < 256)
            s_xs[tid] = s_red[tid] + s_red[256 + tid] +
                        s_red[512 + tid] + s_red[768 + tid];
        __syncthreads();

        float a0 = 0.f, a1 = 0.f, a2 = 0.f, a3 = 0.f;
#pragma unroll
        for (int ii = 0; ii < 8; ++ii) {
            const int il3 = dg * 8 + ii;
            a0 += s_xs[il3]       * w[ii];
            a1 += s_xs[64 + il3]  * w[ii];
            a2 += s_xs[128 + il3] * w[ii];
            a3 += s_xs[192 + il3] * w[ii];
        }
        __syncthreads();
        s_red[(0 * 8 + dg) * 128 + il] = a0;
        s_red[(1 * 8 + dg) * 128 + il] = a1;
        s_red[(2 * 8 + dg) * 128 + il] = a2;
        s_red[(3 * 8 + dg) * 128 + il] = a3;
        __syncthreads();
        if (tid < 512) {
            const int bb = tid >> 7, ol2 = tid & 127;
            float s = 0.f;
#pragma unroll
            for (int g = 0; g < 8; ++g) s += s_red[(bb * 8 + g) * 128 + ol2];
            g_yp[(bb * 16 + ds) * DIM + ic * 128 + ol2] = s;
        }
    }
    bar_arrive(2, gen2);
    bar_wait(2, gen2);

    // ---------------- Phase 4: finalize y[b] + broadcast 64 rows -----------
    {
        const int b  = blk >> 5;
        const int sb = blk & 31;

        float acc = 0.f;
#pragma unroll
        for (int p = 0; p < 16; ++p)
            acc += g_yp[(b * 16 + p) * DIM + tid];
        s_red[tid] = acc;
        __syncthreads();

        const int r4 = tid >> 8, c = tid & 255;
        const float4 v = reinterpret_cast<const float4*>(s_red)[c];
        float4* o4 = reinterpret_cast<float4*>(out)
                   + (size_t)(b * SEQ + sb * 64 + r4) * 256 + c;
#pragma unroll
        for (int r = 0; r < 16; ++r)
            __stcs(&o4[(size_t)r * 4 * 256], v);   // evict-first: drain during P4
    }
}

// Inputs: 0=inputs_embeds [B,S,D] f32, 1=structure_features, 2=Wq, 3=Wk,
// 4=Wv [D,I] f32, 5=Wo [I,D] f32, 6=num_heads. Only x, Wv, Wo matter.
extern "C" void kernel_launch(void* const* d_in, const int* in_sizes, int n_in,
                              void* d_out, int out_size) {
    (void)in_sizes; (void)n_in; (void)out_size;
    const float* x  = (const float*)d_in[0];
    const float* Wv = (const float*)d_in[4];
    const float* Wo = (const float*)d_in[5];
    fusion_persistent<<<NBLK, NTHR>>>(x, Wv, Wo, (float*)d_out);
}